// round 12
// baseline (speedup 1.0000x reference)
#include <cuda_runtime.h>
#include <math.h>

#define N_LEVELS      16
#define HASHMAP_SIZE  (1u << 19)
#define HASH_MASK     (HASHMAP_SIZE - 1u)
#define P2            2654435761u
#define P3            805459861u

struct ResTable {
    int res[N_LEVELS];
};

// 8 lanes per point (one corner each), 4 points per warp.
// Levels processed in 2 batches of 8: indices first, then 8 back-to-back
// gathers (MLP), then the weight+butterfly chain consumes them in order.
__global__ void __launch_bounds__(256, 4)
hashenc_kernel(const float* __restrict__ pos,
               const float* __restrict__ emb,
               float* __restrict__ out,
               ResTable rt,
               int n_points)
{
    const int tid  = blockIdx.x * blockDim.x + threadIdx.x;
    const int lane = threadIdx.x & 31;
    const int c    = lane & 7;          // corner id: (i<<2)|(j<<1)|k
    const int sub  = lane >> 3;         // point slot within warp (0..3)
    const int p    = (tid >> 5) * 4 + sub;

    const bool valid = (p < n_points);
    const int  pp    = valid ? p : 0;

    const unsigned bi = (c >> 2) & 1;
    const unsigned bj = (c >> 1) & 1;
    const unsigned bk =  c       & 1;

    const float px = pos[pp * 3 + 0];
    const float py = pos[pp * 3 + 1];
    const float pz = pos[pp * 3 + 2];

    // lane c keeps results for levels 2c and 2c+1
    float acc0 = 0.f, acc1 = 0.f, acc2 = 0.f, acc3 = 0.f;

#pragma unroll
    for (int batch = 0; batch < 2; ++batch) {
        // ---- phase 1: all 8 indices + weights ----
        const float2* taddr[8];
        float wgt[8];
#pragma unroll
        for (int j = 0; j < 8; ++j) {
            const int l = batch * 8 + j;
            const int   res  = rt.res[l];
            const float fres = (float)res;

            const float sx = px * fres, sy = py * fres, sz = pz * fres;
            const float fx = floorf(sx), fy = floorf(sy), fz = floorf(sz);
            const float wx = sx - fx,   wy = sy - fy,   wz = sz - fz;

            const unsigned ux = (unsigned)(int)fx + bi;
            const unsigned uy = (unsigned)(int)fy + bj;
            const unsigned uz = (unsigned)(int)fz + bk;

            const unsigned r1 = (unsigned)(res + 1);
            const bool dense =
                ((long long)r1 * (long long)r1 * (long long)r1) <= (long long)HASHMAP_SIZE;

            unsigned idx;
            if (dense) {
                idx = ux * (r1 * r1) + uy * r1 + uz;
            } else {
                idx = (ux ^ (uy * P2) ^ (uz * P3)) & HASH_MASK;
            }

            taddr[j] = reinterpret_cast<const float2*>(emb)
                       + (size_t)l * HASHMAP_SIZE + idx;

            const float ax = bi ? wx : (1.0f - wx);
            const float ay = bj ? wy : (1.0f - wy);
            const float az = bk ? wz : (1.0f - wz);
            wgt[j] = ax * ay * az;
        }

        // ---- phase 2: 8 back-to-back gathers (deep MLP) ----
        float2 f[8];
#pragma unroll
        for (int j = 0; j < 8; ++j) {
            f[j] = __ldg(taddr[j]);
        }

        // ---- phase 3: consume in order; f[j] dies after use ----
#pragma unroll
        for (int j = 0; j < 8; ++j) {
            const int l = batch * 8 + j;

            float v0 = f[j].x * wgt[j];
            float v1 = f[j].y * wgt[j];

            v0 += __shfl_xor_sync(0xffffffffu, v0, 4);
            v1 += __shfl_xor_sync(0xffffffffu, v1, 4);
            v0 += __shfl_xor_sync(0xffffffffu, v0, 2);
            v1 += __shfl_xor_sync(0xffffffffu, v1, 2);
            v0 += __shfl_xor_sync(0xffffffffu, v0, 1);
            v1 += __shfl_xor_sync(0xffffffffu, v1, 1);

            if ((l >> 1) == c) {
                if (l & 1) { acc2 = v0; acc3 = v1; }
                else       { acc0 = v0; acc1 = v1; }
            }
        }
    }

    if (valid) {
        float4* __restrict__ o4 = reinterpret_cast<float4*>(out);
        o4[(size_t)p * 8 + c] = make_float4(acc0, acc1, acc2, acc3);
    }
}

extern "C" void kernel_launch(void* const* d_in, const int* in_sizes, int n_in,
                              void* d_out, int out_size)
{
    const float* positions  = (const float*)d_in[0];   // [N_POINTS, 3] f32
    const float* embeddings = (const float*)d_in[1];   // [16, 2^19, 2] f32
    float*       out        = (float*)d_out;           // [N_POINTS, 32] f32

    const int n_points = in_sizes[0] / 3;

    // Mirror numpy exactly in double precision (libm exp/log/pow)
    ResTable rt;
    const double scale = exp((log(2048.0) - log(16.0)) / 15.0);
    for (int l = 0; l < N_LEVELS; ++l) {
        rt.res[l] = (int)floor(16.0 * pow(scale, (double)l));
    }

    const long long total_threads = (long long)n_points * 8;
    const int threads = 256;
    const int blocks  = (int)((total_threads + threads - 1) / threads);
    hashenc_kernel<<<blocks, threads>>>(positions, embeddings, out, rt, n_points);
}

// round 13
// speedup vs baseline: 1.1570x; 1.1570x over previous
#include <cuda_runtime.h>
#include <math.h>

#define N_LEVELS      16
#define HASHMAP_SIZE  (1u << 19)
#define HASH_MASK     (HASHMAP_SIZE - 1u)
#define P2            2654435761u
#define P3            805459861u

struct ResTable {
    int res[N_LEVELS];
};

// 8 lanes per point (one corner each), 4 points per warp.  R5 skeleton.
// Hash levels (l>=5) load with .cg (L2-only, no L1 allocation/fill);
// dense levels (l<=4, tables 39KB..2MB with 0-1 truly L1-resident) keep .nc.
__global__ void __launch_bounds__(256)
hashenc_kernel(const float* __restrict__ pos,
               const float* __restrict__ emb,
               float* __restrict__ out,
               ResTable rt,
               int n_points)
{
    const int tid  = blockIdx.x * blockDim.x + threadIdx.x;
    const int lane = threadIdx.x & 31;
    const int c    = lane & 7;          // corner id: (i<<2)|(j<<1)|k
    const int sub  = lane >> 3;         // point slot within warp (0..3)
    const int p    = (tid >> 5) * 4 + sub;

    const bool valid = (p < n_points);
    const int  pp    = valid ? p : 0;

    const unsigned bi = (c >> 2) & 1;
    const unsigned bj = (c >> 1) & 1;
    const unsigned bk =  c       & 1;

    const float px = pos[pp * 3 + 0];
    const float py = pos[pp * 3 + 1];
    const float pz = pos[pp * 3 + 2];

    // lane c keeps results for levels 2c and 2c+1
    float acc0 = 0.f, acc1 = 0.f, acc2 = 0.f, acc3 = 0.f;

#pragma unroll
    for (int l = 0; l < N_LEVELS; ++l) {
        const int   res  = rt.res[l];
        const float fres = (float)res;

        const float sx = px * fres, sy = py * fres, sz = pz * fres;
        const float fx = floorf(sx), fy = floorf(sy), fz = floorf(sz);
        const float wx = sx - fx,   wy = sy - fy,   wz = sz - fz;

        const unsigned ux = (unsigned)(int)fx + bi;
        const unsigned uy = (unsigned)(int)fy + bj;
        const unsigned uz = (unsigned)(int)fz + bk;

        const unsigned r1 = (unsigned)(res + 1);
        const bool dense =
            ((long long)r1 * (long long)r1 * (long long)r1) <= (long long)HASHMAP_SIZE;

        unsigned idx;
        if (dense) {
            idx = ux * (r1 * r1) + uy * r1 + uz;
        } else {
            idx = (ux ^ (uy * P2) ^ (uz * P3)) & HASH_MASK;
        }

        const float2* __restrict__ table =
            reinterpret_cast<const float2*>(emb) + (size_t)l * HASHMAP_SIZE;

        float2 f;
        if (l <= 4) {
            f = __ldg(&table[idx]);        // dense/coarse: cache in L1
        } else {
            f = __ldcg(&table[idx]);       // hash: L2 only, no L1 fill
        }

        const float ax = bi ? wx : (1.0f - wx);
        const float ay = bj ? wy : (1.0f - wy);
        const float az = bk ? wz : (1.0f - wz);
        const float w  = ax * ay * az;

        float v0 = f.x * w;
        float v1 = f.y * w;

        v0 += __shfl_xor_sync(0xffffffffu, v0, 4);
        v1 += __shfl_xor_sync(0xffffffffu, v1, 4);
        v0 += __shfl_xor_sync(0xffffffffu, v0, 2);
        v1 += __shfl_xor_sync(0xffffffffu, v1, 2);
        v0 += __shfl_xor_sync(0xffffffffu, v0, 1);
        v1 += __shfl_xor_sync(0xffffffffu, v1, 1);

        if ((l >> 1) == c) {
            if (l & 1) { acc2 = v0; acc3 = v1; }
            else       { acc0 = v0; acc1 = v1; }
        }
    }

    if (valid) {
        float4* __restrict__ o4 = reinterpret_cast<float4*>(out);
        o4[(size_t)p * 8 + c] = make_float4(acc0, acc1, acc2, acc3);
    }
}

extern "C" void kernel_launch(void* const* d_in, const int* in_sizes, int n_in,
                              void* d_out, int out_size)
{
    const float* positions  = (const float*)d_in[0];   // [N_POINTS, 3] f32
    const float* embeddings = (const float*)d_in[1];   // [16, 2^19, 2] f32
    float*       out        = (float*)d_out;           // [N_POINTS, 32] f32

    const int n_points = in_sizes[0] / 3;

    // Mirror numpy exactly in double precision (libm exp/log/pow)
    ResTable rt;
    const double scale = exp((log(2048.0) - log(16.0)) / 15.0);
    for (int l = 0; l < N_LEVELS; ++l) {
        rt.res[l] = (int)floor(16.0 * pow(scale, (double)l));
    }

    const long long total_threads = (long long)n_points * 8;
    const int threads = 256;
    const int blocks  = (int)((total_threads + threads - 1) / threads);
    hashenc_kernel<<<blocks, threads>>>(positions, embeddings, out, rt, n_points);
}

// round 14
// speedup vs baseline: 1.1613x; 1.0038x over previous
#include <cuda_runtime.h>
#include <math.h>

#define N_LEVELS      16
#define HASHMAP_SIZE  (1u << 19)
#define HASH_MASK     (HASHMAP_SIZE - 1u)
#define P2            2654435761u
#define P3            805459861u

struct ResTable {
    int res[N_LEVELS];
};

// 8 lanes per point (one corner each), 4 points per warp.  R5/R13 skeleton.
// L1 policy: only levels 0-1 (39KB+125KB, together L1-resident) allocate in
// L1 (.nc); all other levels bypass L1 (.cg) so they never evict them.
__global__ void __launch_bounds__(256)
hashenc_kernel(const float* __restrict__ pos,
               const float* __restrict__ emb,
               float* __restrict__ out,
               ResTable rt,
               int n_points)
{
    const int tid  = blockIdx.x * blockDim.x + threadIdx.x;
    const int lane = threadIdx.x & 31;
    const int c    = lane & 7;          // corner id: (i<<2)|(j<<1)|k
    const int sub  = lane >> 3;         // point slot within warp (0..3)
    const int p    = (tid >> 5) * 4 + sub;

    const bool valid = (p < n_points);
    const int  pp    = valid ? p : 0;

    const unsigned bi = (c >> 2) & 1;
    const unsigned bj = (c >> 1) & 1;
    const unsigned bk =  c       & 1;

    // weight via FMA: a = s*w + o  (s=+1,o=0 if corner bit set; s=-1,o=1 else)
    const float sxw = bi ? 1.f : -1.f, oxw = bi ? 0.f : 1.f;
    const float syw = bj ? 1.f : -1.f, oyw = bj ? 0.f : 1.f;
    const float szw = bk ? 1.f : -1.f, ozw = bk ? 0.f : 1.f;

    const float px = pos[pp * 3 + 0];
    const float py = pos[pp * 3 + 1];
    const float pz = pos[pp * 3 + 2];

    // lane c keeps results for levels 2c and 2c+1
    float acc0 = 0.f, acc1 = 0.f, acc2 = 0.f, acc3 = 0.f;

#pragma unroll
    for (int l = 0; l < N_LEVELS; ++l) {
        const int   res  = rt.res[l];
        const float fres = (float)res;

        const float sx = px * fres, sy = py * fres, sz = pz * fres;
        const float fx = floorf(sx), fy = floorf(sy), fz = floorf(sz);
        const float wx = sx - fx,   wy = sy - fy,   wz = sz - fz;

        const unsigned ux = (unsigned)(int)fx + bi;
        const unsigned uy = (unsigned)(int)fy + bj;
        const unsigned uz = (unsigned)(int)fz + bk;

        const unsigned r1 = (unsigned)(res + 1);
        const bool dense =
            ((long long)r1 * (long long)r1 * (long long)r1) <= (long long)HASHMAP_SIZE;

        unsigned idx;
        if (dense) {
            idx = ux * (r1 * r1) + uy * r1 + uz;
        } else {
            idx = (ux ^ (uy * P2) ^ (uz * P3)) & HASH_MASK;
        }

        const float2* __restrict__ table =
            reinterpret_cast<const float2*>(emb) + (size_t)l * HASHMAP_SIZE;

        float2 f;
        if (l <= 1) {
            f = __ldg(&table[idx]);        // L1-resident coarse tables
        } else {
            f = __ldcg(&table[idx]);       // L2 only: never evict levels 0-1
        }

        const float ax = fmaf(sxw, wx, oxw);
        const float ay = fmaf(syw, wy, oyw);
        const float az = fmaf(szw, wz, ozw);
        const float w  = ax * ay * az;

        float v0 = f.x * w;
        float v1 = f.y * w;

        v0 += __shfl_xor_sync(0xffffffffu, v0, 4);
        v1 += __shfl_xor_sync(0xffffffffu, v1, 4);
        v0 += __shfl_xor_sync(0xffffffffu, v0, 2);
        v1 += __shfl_xor_sync(0xffffffffu, v1, 2);
        v0 += __shfl_xor_sync(0xffffffffu, v0, 1);
        v1 += __shfl_xor_sync(0xffffffffu, v1, 1);

        if ((l >> 1) == c) {
            if (l & 1) { acc2 = v0; acc3 = v1; }
            else       { acc0 = v0; acc1 = v1; }
        }
    }

    if (valid) {
        float4* __restrict__ o4 = reinterpret_cast<float4*>(out);
        o4[(size_t)p * 8 + c] = make_float4(acc0, acc1, acc2, acc3);
    }
}

extern "C" void kernel_launch(void* const* d_in, const int* in_sizes, int n_in,
                              void* d_out, int out_size)
{
    const float* positions  = (const float*)d_in[0];   // [N_POINTS, 3] f32
    const float* embeddings = (const float*)d_in[1];   // [16, 2^19, 2] f32
    float*       out        = (float*)d_out;           // [N_POINTS, 32] f32

    const int n_points = in_sizes[0] / 3;

    // Mirror numpy exactly in double precision (libm exp/log/pow)
    ResTable rt;
    const double scale = exp((log(2048.0) - log(16.0)) / 15.0);
    for (int l = 0; l < N_LEVELS; ++l) {
        rt.res[l] = (int)floor(16.0 * pow(scale, (double)l));
    }

    const long long total_threads = (long long)n_points * 8;
    const int threads = 256;
    const int blocks  = (int)((total_threads + threads - 1) / threads);
    hashenc_kernel<<<blocks, threads>>>(positions, embeddings, out, rt, n_points);
}